// round 1
// baseline (speedup 1.0000x reference)
#include <cuda_runtime.h>

#define NPIX 4096
#define BT 2

// 50*log2(e), 25*log2(e), log2(e)
#define C50F   72.13475204444817f
#define C25F   36.067376022224085f
#define CL2E   1.4426950408889634f

// ---------------------------------------------------------------------------
// Scratch (device globals; no allocations allowed)
// ---------------------------------------------------------------------------
__device__ float  g_ux[BT][NPIX];
__device__ float  g_uy[BT][NPIX];
__device__ float  g_uz[BT][NPIX];
// per-i record: [0] = (a0,a1,a2,|a|^2)   [1] = (fs0,fs1,fs2, L2row)
__device__ float4 g_iRec[BT][NPIX][2];
// per-j record: [0] = (u0,u1,u2, LSEcol2) [1] = (ft*log2e x3, 0) [2] = (fs0,fs1,fs2,0)
__device__ float4 g_jRec[BT][NPIX][3];

// ---------------------------------------------------------------------------
// Helpers
// ---------------------------------------------------------------------------
__device__ __forceinline__ float ex2f(float x) {
    float y;
    asm("ex2.approx.ftz.f32 %0, %1;" : "=f"(y) : "f"(x));
    return y;
}
__device__ __forceinline__ float wsum(float v) {
    #pragma unroll
    for (int o = 16; o; o >>= 1) v += __shfl_xor_sync(0xffffffffu, v, o);
    return v;
}
__device__ __forceinline__ float wmin(float v) {
    #pragma unroll
    for (int o = 16; o; o >>= 1) v = fminf(v, __shfl_xor_sync(0xffffffffu, v, o));
    return v;
}

// ---------------------------------------------------------------------------
// Precompute per-i / per-j records (tiny; double precision for geometry)
// ---------------------------------------------------------------------------
__global__ void k_pre(const float* __restrict__ f_tar, const float* __restrict__ f_src,
                      const float* __restrict__ Km, const float* __restrict__ Rm,
                      const float* __restrict__ tv) {
    int b = blockIdx.x;
    double Kd[9], Rd[9], td[3];
    #pragma unroll
    for (int m = 0; m < 9; m++) { Kd[m] = (double)Km[b*9+m]; Rd[m] = (double)Rm[b*9+m]; }
    #pragma unroll
    for (int m = 0; m < 3; m++) td[m] = (double)tv[b*3+m];

    // K inverse (adjugate / det)
    double c00 = Kd[4]*Kd[8] - Kd[5]*Kd[7];
    double c10 = Kd[5]*Kd[6] - Kd[3]*Kd[8];
    double c20 = Kd[3]*Kd[7] - Kd[4]*Kd[6];
    double det = Kd[0]*c00 + Kd[1]*c10 + Kd[2]*c20;
    double id  = 1.0 / det;
    double Ki[9];
    Ki[0] = c00*id; Ki[1] = (Kd[2]*Kd[7]-Kd[1]*Kd[8])*id; Ki[2] = (Kd[1]*Kd[5]-Kd[2]*Kd[4])*id;
    Ki[3] = c10*id; Ki[4] = (Kd[0]*Kd[8]-Kd[2]*Kd[6])*id; Ki[5] = (Kd[2]*Kd[3]-Kd[0]*Kd[5])*id;
    Ki[6] = c20*id; Ki[7] = (Kd[1]*Kd[6]-Kd[0]*Kd[7])*id; Ki[8] = (Kd[0]*Kd[4]-Kd[1]*Kd[3])*id;

    // o = K @ t
    double o0 = Kd[0]*td[0] + Kd[1]*td[1] + Kd[2]*td[2];
    double o1 = Kd[3]*td[0] + Kd[4]*td[1] + Kd[5]*td[2];
    double o2 = Kd[6]*td[0] + Kd[7]*td[1] + Kd[8]*td[2];
    float of0 = (float)o0, of1 = (float)o1, of2 = (float)o2;

    const float* fs = f_src + b*3*NPIX;
    const float* ft = f_tar + b*3*NPIX;

    for (int j = threadIdx.x; j < NPIX; j += blockDim.x) {
        // diff_j = K(R(Kinv pix) + t) - K t ; u = diff/|diff|
        double px = (double)(j >> 6), py = (double)(j & 63);
        double ca = Ki[0]*px + Ki[1]*py + Ki[2];
        double cb = Ki[3]*px + Ki[4]*py + Ki[5];
        double cc = Ki[6]*px + Ki[7]*py + Ki[8];
        double ra = Rd[0]*ca + Rd[1]*cb + Rd[2]*cc + td[0];
        double rb = Rd[3]*ca + Rd[4]*cb + Rd[5]*cc + td[1];
        double rc = Rd[6]*ca + Rd[7]*cb + Rd[8]*cc + td[2];
        double da = Kd[0]*ra + Kd[1]*rb + Kd[2]*rc - o0;
        double db = Kd[3]*ra + Kd[4]*rb + Kd[5]*rc - o1;
        double dc = Kd[6]*ra + Kd[7]*rb + Kd[8]*rc - o2;
        double inv = 1.0 / sqrt(da*da + db*db + dc*dc);
        float u0 = (float)(da*inv), u1 = (float)(db*inv), u2 = (float)(dc*inv);
        g_ux[b][j] = u0; g_uy[b][j] = u1; g_uz[b][j] = u2;

        float t0 = ft[j], t1 = ft[NPIX + j], t2 = ft[2*NPIX + j];
        float s0 = fs[j], s1 = fs[NPIX + j], s2 = fs[2*NPIX + j];
        g_jRec[b][j][0] = make_float4(u0, u1, u2, 0.f);
        g_jRec[b][j][1] = make_float4(t0*CL2E, t1*CL2E, t2*CL2E, 0.f);
        g_jRec[b][j][2] = make_float4(s0, s1, s2, 0.f);

        // per-i record (i == j loop variable; same range)
        float a0 = s0 - of0, a1 = s1 - of1, a2 = s2 - of2;
        float na2 = (float)((double)a0*a0 + (double)a1*a1 + (double)a2*a2);
        g_iRec[b][j][0] = make_float4(a0, a1, a2, na2);
        g_iRec[b][j][1] = make_float4(s0, s1, s2, 0.f);
    }
}

// ---------------------------------------------------------------------------
// Pass 1: row LSE of s_ij (base-2). Warp = 2 rows; sweep A = max via min dot^2
// (no MUFU), sweep B = sum of ex2.
// ---------------------------------------------------------------------------
__global__ void k_rowstats() {
    int b = blockIdx.x;
    int warp = threadIdx.x >> 5, lane = threadIdx.x & 31;
    int i0 = blockIdx.y * 16 + warp * 2;

    float4 A0 = g_iRec[b][i0][0];
    float4 A1 = g_iRec[b][i0+1][0];
    const float4* X4 = (const float4*)g_ux[b];
    const float4* Y4 = (const float4*)g_uy[b];
    const float4* Z4 = (const float4*)g_uz[b];

    float m0 = 3.4e38f, m1 = 3.4e38f;
    for (int it = lane; it < NPIX/4; it += 32) {
        float4 X = __ldg(X4 + it), Y = __ldg(Y4 + it), Z = __ldg(Z4 + it);
        float ux[4] = {X.x, X.y, X.z, X.w};
        float uy[4] = {Y.x, Y.y, Y.z, Y.w};
        float uz[4] = {Z.x, Z.y, Z.z, Z.w};
        #pragma unroll
        for (int k = 0; k < 4; k++) {
            float d0 = fmaf(A0.x, ux[k], fmaf(A0.y, uy[k], A0.z*uz[k]));
            m0 = fminf(m0, d0*d0);
            float d1 = fmaf(A1.x, ux[k], fmaf(A1.y, uy[k], A1.z*uz[k]));
            m1 = fminf(m1, d1*d1);
        }
    }
    m0 = wmin(m0); m1 = wmin(m1);
    float cM0 = __fsqrt_rn(fmaxf(A0.w - m0, 0.f)) * C50F;  // = max_j (d*C50)
    float cM1 = __fsqrt_rn(fmaxf(A1.w - m1, 0.f)) * C50F;

    float s0 = 0.f, s1 = 0.f;
    for (int it = lane; it < NPIX/4; it += 32) {
        float4 X = __ldg(X4 + it), Y = __ldg(Y4 + it), Z = __ldg(Z4 + it);
        float ux[4] = {X.x, X.y, X.z, X.w};
        float uy[4] = {Y.x, Y.y, Y.z, Y.w};
        float uz[4] = {Z.x, Z.y, Z.z, Z.w};
        #pragma unroll
        for (int k = 0; k < 4; k++) {
            float d0 = fmaf(A0.x, ux[k], fmaf(A0.y, uy[k], A0.z*uz[k]));
            float q0 = fmaxf(fmaf(-d0, d0, A0.w), 0.f);
            s0 += ex2f(fmaf(__fsqrt_rn(q0), C50F, -cM0));
            float d1 = fmaf(A1.x, ux[k], fmaf(A1.y, uy[k], A1.z*uz[k]));
            float q1 = fmaxf(fmaf(-d1, d1, A1.w), 0.f);
            s1 += ex2f(fmaf(__fsqrt_rn(q1), C50F, -cM1));
        }
    }
    s0 = wsum(s0); s1 = wsum(s1);
    if (lane == 0) {
        // L2row = M2 + log2(S) = (cM - C25) + log2(S)
        ((float*)&g_iRec[b][i0][1])[3]   = (cM0 - C25F) + log2f(s0);
        ((float*)&g_iRec[b][i0+1][1])[3] = (cM1 - C25F) + log2f(s1);
    }
}

// ---------------------------------------------------------------------------
// Pass 2: column log2-sum of exp2(AW * log2e). Warp = 4 columns, lanes over i.
// AW bounded (|A| <= ~20) so no max-shift needed.
// ---------------------------------------------------------------------------
__global__ void k_colstats() {
    int b = blockIdx.x;
    int warp = threadIdx.x >> 5, lane = threadIdx.x & 31;
    int jb = blockIdx.y * 32 + warp * 4;

    float u0[4], u1[4], u2[4], t0[4], t1[4], t2[4];
    #pragma unroll
    for (int c = 0; c < 4; c++) {
        float4 J0 = g_jRec[b][jb+c][0]; u0[c] = J0.x; u1[c] = J0.y; u2[c] = J0.z;
        float4 J1 = g_jRec[b][jb+c][1]; t0[c] = J1.x; t1[c] = J1.y; t2[c] = J1.z;
    }
    float acc[4] = {0.f, 0.f, 0.f, 0.f};

    for (int i = lane; i < NPIX; i += 32) {
        float4 A = __ldg(&g_iRec[b][i][0]);
        float4 F = __ldg(&g_iRec[b][i][1]);
        float cL = C25F + F.w;
        #pragma unroll
        for (int c = 0; c < 4; c++) {
            float d = fmaf(A.x, u0[c], fmaf(A.y, u1[c], A.z*u2[c]));
            float q = fmaxf(fmaf(-d, d, A.w), 0.f);
            float w = 1.f - ex2f(fmaf(__fsqrt_rn(q), C50F, -cL));
            float a2 = fmaf(F.x, t0[c], fmaf(F.y, t1[c], F.z*t2[c]));  // A*log2e
            acc[c] += ex2f(a2 * w);
        }
    }
    #pragma unroll
    for (int c = 0; c < 4; c++) {
        float s = wsum(acc[c]);
        if (lane == 0) ((float*)&g_jRec[b][jb+c][0])[3] = log2f(s);
    }
}

// ---------------------------------------------------------------------------
// Pass 3: out[b,i,c] = sum_j exp2(AW2_ij - LSEcol2_j) * fs[c,j]
// Warp = 4 rows, lanes over j.
// ---------------------------------------------------------------------------
__global__ void k_out(float* __restrict__ out) {
    int b = blockIdx.x;
    int warp = threadIdx.x >> 5, lane = threadIdx.x & 31;
    int ib = blockIdx.y * 32 + warp * 4;

    float ax[4], ay[4], az[4], an[4], fx[4], fy[4], fz[4], cL[4];
    float o0[4] = {0,0,0,0}, o1[4] = {0,0,0,0}, o2[4] = {0,0,0,0};
    #pragma unroll
    for (int r = 0; r < 4; r++) {
        float4 A = g_iRec[b][ib+r][0]; ax[r] = A.x; ay[r] = A.y; az[r] = A.z; an[r] = A.w;
        float4 F = g_iRec[b][ib+r][1]; fx[r] = F.x; fy[r] = F.y; fz[r] = F.z; cL[r] = C25F + F.w;
    }

    for (int j = lane; j < NPIX; j += 32) {
        float4 J0 = __ldg(&g_jRec[b][j][0]);  // u, LSEcol2
        float4 J1 = __ldg(&g_jRec[b][j][1]);  // ft * log2e
        float4 J2 = __ldg(&g_jRec[b][j][2]);  // fs_j
        #pragma unroll
        for (int r = 0; r < 4; r++) {
            float d = fmaf(ax[r], J0.x, fmaf(ay[r], J0.y, az[r]*J0.z));
            float q = fmaxf(fmaf(-d, d, an[r]), 0.f);
            float w = 1.f - ex2f(fmaf(__fsqrt_rn(q), C50F, -cL[r]));
            float a2 = fmaf(fx[r], J1.x, fmaf(fy[r], J1.y, fz[r]*J1.z));
            float p = ex2f(a2 * w - J0.w);
            o0[r] = fmaf(p, J2.x, o0[r]);
            o1[r] = fmaf(p, J2.y, o1[r]);
            o2[r] = fmaf(p, J2.z, o2[r]);
        }
    }
    #pragma unroll
    for (int r = 0; r < 4; r++) {
        float v0 = wsum(o0[r]), v1 = wsum(o1[r]), v2 = wsum(o2[r]);
        if (lane == 0) {
            int base = b*NPIX*3 + (ib + r)*3;   // (B,N,C) layout == output reshape
            out[base]   = v0;
            out[base+1] = v1;
            out[base+2] = v2;
        }
    }
}

// ---------------------------------------------------------------------------
extern "C" void kernel_launch(void* const* d_in, const int* in_sizes, int n_in,
                              void* d_out, int out_size) {
    const float* f_tar = (const float*)d_in[0];
    const float* f_src = (const float*)d_in[1];
    const float* Km    = (const float*)d_in[2];
    const float* Rm    = (const float*)d_in[3];
    const float* tv    = (const float*)d_in[4];
    float* out = (float*)d_out;

    k_pre<<<BT, 256>>>(f_tar, f_src, Km, Rm, tv);
    k_rowstats<<<dim3(BT, NPIX/16), 256>>>();
    k_colstats<<<dim3(BT, NPIX/32), 256>>>();
    k_out<<<dim3(BT, NPIX/32), 256>>>(out);
}

// round 2
// speedup vs baseline: 1.4080x; 1.4080x over previous
#include <cuda_runtime.h>

#define NPIX 4096
#define BT 2

// 50*log2(e), 25*log2(e), log2(e)
#define C50F   72.13475204444817f
#define C25F   36.067376022224085f
#define CL2E   1.4426950408889634f

// ---------------------------------------------------------------------------
// Scratch (device globals; no allocations allowed)
// ---------------------------------------------------------------------------
__device__ float  g_ux[BT][NPIX];
__device__ float  g_uy[BT][NPIX];
__device__ float  g_uz[BT][NPIX];
// per-i record: [0] = (a0,a1,a2,|a|^2)   [1] = (fs0,fs1,fs2, L2row)
__device__ float4 g_iRec[BT][NPIX][2];
// per-j record: [0] = (u0,u1,u2, LSEcol2) [1] = (ft*log2e x3, 0) [2] = (fs0,fs1,fs2,0)
__device__ float4 g_jRec[BT][NPIX][3];

// ---------------------------------------------------------------------------
// Helpers
// ---------------------------------------------------------------------------
__device__ __forceinline__ float ex2f(float x) {
    float y;
    asm("ex2.approx.ftz.f32 %0, %1;" : "=f"(y) : "f"(x));
    return y;
}
__device__ __forceinline__ float sqapx(float x) {
    float y;
    asm("sqrt.approx.ftz.f32 %0, %1;" : "=f"(y) : "f"(x));
    return y;
}
__device__ __forceinline__ float wsum(float v) {
    #pragma unroll
    for (int o = 16; o; o >>= 1) v += __shfl_xor_sync(0xffffffffu, v, o);
    return v;
}
__device__ __forceinline__ float wmin(float v) {
    #pragma unroll
    for (int o = 16; o; o >>= 1) v = fminf(v, __shfl_xor_sync(0xffffffffu, v, o));
    return v;
}

// ---------------------------------------------------------------------------
// Precompute per-i / per-j records (tiny; double precision for geometry)
// ---------------------------------------------------------------------------
__global__ void k_pre(const float* __restrict__ f_tar, const float* __restrict__ f_src,
                      const float* __restrict__ Km, const float* __restrict__ Rm,
                      const float* __restrict__ tv) {
    int b = blockIdx.x;
    double Kd[9], Rd[9], td[3];
    #pragma unroll
    for (int m = 0; m < 9; m++) { Kd[m] = (double)Km[b*9+m]; Rd[m] = (double)Rm[b*9+m]; }
    #pragma unroll
    for (int m = 0; m < 3; m++) td[m] = (double)tv[b*3+m];

    double c00 = Kd[4]*Kd[8] - Kd[5]*Kd[7];
    double c10 = Kd[5]*Kd[6] - Kd[3]*Kd[8];
    double c20 = Kd[3]*Kd[7] - Kd[4]*Kd[6];
    double det = Kd[0]*c00 + Kd[1]*c10 + Kd[2]*c20;
    double id  = 1.0 / det;
    double Ki[9];
    Ki[0] = c00*id; Ki[1] = (Kd[2]*Kd[7]-Kd[1]*Kd[8])*id; Ki[2] = (Kd[1]*Kd[5]-Kd[2]*Kd[4])*id;
    Ki[3] = c10*id; Ki[4] = (Kd[0]*Kd[8]-Kd[2]*Kd[6])*id; Ki[5] = (Kd[2]*Kd[3]-Kd[0]*Kd[5])*id;
    Ki[6] = c20*id; Ki[7] = (Kd[1]*Kd[6]-Kd[0]*Kd[7])*id; Ki[8] = (Kd[0]*Kd[4]-Kd[1]*Kd[3])*id;

    double o0 = Kd[0]*td[0] + Kd[1]*td[1] + Kd[2]*td[2];
    double o1 = Kd[3]*td[0] + Kd[4]*td[1] + Kd[5]*td[2];
    double o2 = Kd[6]*td[0] + Kd[7]*td[1] + Kd[8]*td[2];
    float of0 = (float)o0, of1 = (float)o1, of2 = (float)o2;

    const float* fs = f_src + b*3*NPIX;
    const float* ft = f_tar + b*3*NPIX;

    for (int j = threadIdx.x; j < NPIX; j += blockDim.x) {
        double px = (double)(j >> 6), py = (double)(j & 63);
        double ca = Ki[0]*px + Ki[1]*py + Ki[2];
        double cb = Ki[3]*px + Ki[4]*py + Ki[5];
        double cc = Ki[6]*px + Ki[7]*py + Ki[8];
        double ra = Rd[0]*ca + Rd[1]*cb + Rd[2]*cc + td[0];
        double rb = Rd[3]*ca + Rd[4]*cb + Rd[5]*cc + td[1];
        double rc = Rd[6]*ca + Rd[7]*cb + Rd[8]*cc + td[2];
        double da = Kd[0]*ra + Kd[1]*rb + Kd[2]*rc - o0;
        double db = Kd[3]*ra + Kd[4]*rb + Kd[5]*rc - o1;
        double dc = Kd[6]*ra + Kd[7]*rb + Kd[8]*rc - o2;
        double inv = 1.0 / sqrt(da*da + db*db + dc*dc);
        float u0 = (float)(da*inv), u1 = (float)(db*inv), u2 = (float)(dc*inv);
        g_ux[b][j] = u0; g_uy[b][j] = u1; g_uz[b][j] = u2;

        float t0 = ft[j], t1 = ft[NPIX + j], t2 = ft[2*NPIX + j];
        float s0 = fs[j], s1 = fs[NPIX + j], s2 = fs[2*NPIX + j];
        g_jRec[b][j][0] = make_float4(u0, u1, u2, 0.f);
        g_jRec[b][j][1] = make_float4(t0*CL2E, t1*CL2E, t2*CL2E, 0.f);
        g_jRec[b][j][2] = make_float4(s0, s1, s2, 0.f);

        float a0 = s0 - of0, a1 = s1 - of1, a2 = s2 - of2;
        float na2 = (float)((double)a0*a0 + (double)a1*a1 + (double)a2*a2);
        g_iRec[b][j][0] = make_float4(a0, a1, a2, na2);
        g_iRec[b][j][1] = make_float4(s0, s1, s2, 0.f);
    }
}

// ---------------------------------------------------------------------------
// Pass 1: row LSE of s_ij (base-2). Block = 8 warps, handles 8 rows.
// Warp w: rows (w&3)*2, j-half = w>>2 (2048 elems). Partial-LSE merge in smem.
// ---------------------------------------------------------------------------
__global__ void k_rowstats() {
    __shared__ float sM[2][8], sS[2][8];
    int b = blockIdx.x;
    int w = threadIdx.x >> 5, lane = threadIdx.x & 31;
    int half = w >> 2;
    int rloc = (w & 3) * 2;
    int i0 = blockIdx.y * 8 + rloc;

    float4 A0 = g_iRec[b][i0][0];
    float4 A1 = g_iRec[b][i0+1][0];
    const float4* X4 = (const float4*)g_ux[b];
    const float4* Y4 = (const float4*)g_uy[b];
    const float4* Z4 = (const float4*)g_uz[b];

    int itBeg = half * 512 + lane;
    int itEnd = half * 512 + 512;

    float m0 = 3.4e38f, m1 = 3.4e38f;
    for (int it = itBeg; it < itEnd; it += 32) {
        float4 X = __ldg(X4 + it), Y = __ldg(Y4 + it), Z = __ldg(Z4 + it);
        float ux[4] = {X.x, X.y, X.z, X.w};
        float uy[4] = {Y.x, Y.y, Y.z, Y.w};
        float uz[4] = {Z.x, Z.y, Z.z, Z.w};
        #pragma unroll
        for (int k = 0; k < 4; k++) {
            float d0 = fmaf(A0.x, ux[k], fmaf(A0.y, uy[k], A0.z*uz[k]));
            m0 = fminf(m0, d0*d0);
            float d1 = fmaf(A1.x, ux[k], fmaf(A1.y, uy[k], A1.z*uz[k]));
            m1 = fminf(m1, d1*d1);
        }
    }
    m0 = wmin(m0); m1 = wmin(m1);
    float cM0 = sqapx(fmaxf(A0.w - m0, 0.f)) * C50F;  // per-half max of d*C50
    float cM1 = sqapx(fmaxf(A1.w - m1, 0.f)) * C50F;

    float s0 = 0.f, s1 = 0.f;
    for (int it = itBeg; it < itEnd; it += 32) {
        float4 X = __ldg(X4 + it), Y = __ldg(Y4 + it), Z = __ldg(Z4 + it);
        float ux[4] = {X.x, X.y, X.z, X.w};
        float uy[4] = {Y.x, Y.y, Y.z, Y.w};
        float uz[4] = {Z.x, Z.y, Z.z, Z.w};
        #pragma unroll
        for (int k = 0; k < 4; k++) {
            float d0 = fmaf(A0.x, ux[k], fmaf(A0.y, uy[k], A0.z*uz[k]));
            float q0 = fmaxf(fmaf(-d0, d0, A0.w), 0.f);
            s0 += ex2f(fmaf(sqapx(q0), C50F, -cM0));
            float d1 = fmaf(A1.x, ux[k], fmaf(A1.y, uy[k], A1.z*uz[k]));
            float q1 = fmaxf(fmaf(-d1, d1, A1.w), 0.f);
            s1 += ex2f(fmaf(sqapx(q1), C50F, -cM1));
        }
    }
    s0 = wsum(s0); s1 = wsum(s1);
    if (lane == 0) {
        sM[half][rloc]   = cM0; sS[half][rloc]   = s0;
        sM[half][rloc+1] = cM1; sS[half][rloc+1] = s1;
    }
    __syncthreads();
    if (threadIdx.x < 8) {
        int r = threadIdx.x;
        float M0 = sM[0][r], M1 = sM[1][r], S0 = sS[0][r], S1 = sS[1][r];
        float M = fmaxf(M0, M1);
        float S = S0 * ex2f(M0 - M) + S1 * ex2f(M1 - M);
        ((float*)&g_iRec[b][blockIdx.y*8 + r][1])[3] = (M - C25F) + log2f(S);
    }
}

// ---------------------------------------------------------------------------
// Pass 2: column log2-sum of exp2(AW * log2e). Block = 8 warps, 8 cols.
// Warp w: cols (w&1)*4, i-quarter = w>>1 (1024 elems). Sum combine in smem.
// ---------------------------------------------------------------------------
__global__ void k_colstats() {
    __shared__ float sAcc[4][8];
    int b = blockIdx.x;
    int w = threadIdx.x >> 5, lane = threadIdx.x & 31;
    int cg = w & 1;
    int sp = w >> 1;
    int jb = blockIdx.y * 8 + cg * 4;

    float u0[4], u1[4], u2[4], t0[4], t1[4], t2[4];
    #pragma unroll
    for (int c = 0; c < 4; c++) {
        float4 J0 = g_jRec[b][jb+c][0]; u0[c] = J0.x; u1[c] = J0.y; u2[c] = J0.z;
        float4 J1 = g_jRec[b][jb+c][1]; t0[c] = J1.x; t1[c] = J1.y; t2[c] = J1.z;
    }
    float acc[4] = {0.f, 0.f, 0.f, 0.f};

    int iEnd = sp * 1024 + 1024;
    for (int i = sp * 1024 + lane; i < iEnd; i += 32) {
        float4 A = __ldg(&g_iRec[b][i][0]);
        float4 F = __ldg(&g_iRec[b][i][1]);
        float cL = C25F + F.w;
        #pragma unroll
        for (int c = 0; c < 4; c++) {
            float d = fmaf(A.x, u0[c], fmaf(A.y, u1[c], A.z*u2[c]));
            float q = fmaxf(fmaf(-d, d, A.w), 0.f);
            float wgt = 1.f - ex2f(fmaf(sqapx(q), C50F, -cL));
            float a2 = fmaf(F.x, t0[c], fmaf(F.y, t1[c], F.z*t2[c]));
            acc[c] += ex2f(a2 * wgt);
        }
    }
    #pragma unroll
    for (int c = 0; c < 4; c++) {
        float s = wsum(acc[c]);
        if (lane == 0) sAcc[sp][cg*4 + c] = s;
    }
    __syncthreads();
    if (threadIdx.x < 8) {
        int c = threadIdx.x;
        float s = sAcc[0][c] + sAcc[1][c] + sAcc[2][c] + sAcc[3][c];
        ((float*)&g_jRec[b][blockIdx.y*8 + c][0])[3] = log2f(s);
    }
}

// ---------------------------------------------------------------------------
// Pass 3: out[b,i,c] = sum_j exp2(AW2_ij - LSEcol2_j) * fs[c,j]
// Block = 8 warps, 8 rows. Warp w: rows (w&1)*4, j-quarter = w>>1.
// ---------------------------------------------------------------------------
__global__ void k_out(float* __restrict__ out) {
    __shared__ float sO[4][8][3];
    int b = blockIdx.x;
    int w = threadIdx.x >> 5, lane = threadIdx.x & 31;
    int rg = w & 1;
    int sp = w >> 1;
    int ib = blockIdx.y * 8 + rg * 4;

    float ax[4], ay[4], az[4], an[4], fx[4], fy[4], fz[4], cL[4];
    float o0[4] = {0,0,0,0}, o1[4] = {0,0,0,0}, o2[4] = {0,0,0,0};
    #pragma unroll
    for (int r = 0; r < 4; r++) {
        float4 A = g_iRec[b][ib+r][0]; ax[r] = A.x; ay[r] = A.y; az[r] = A.z; an[r] = A.w;
        float4 F = g_iRec[b][ib+r][1]; fx[r] = F.x; fy[r] = F.y; fz[r] = F.z; cL[r] = C25F + F.w;
    }

    int jEnd = sp * 1024 + 1024;
    for (int j = sp * 1024 + lane; j < jEnd; j += 32) {
        float4 J0 = __ldg(&g_jRec[b][j][0]);  // u, LSEcol2
        float4 J1 = __ldg(&g_jRec[b][j][1]);  // ft * log2e
        float4 J2 = __ldg(&g_jRec[b][j][2]);  // fs_j
        #pragma unroll
        for (int r = 0; r < 4; r++) {
            float d = fmaf(ax[r], J0.x, fmaf(ay[r], J0.y, az[r]*J0.z));
            float q = fmaxf(fmaf(-d, d, an[r]), 0.f);
            float wgt = 1.f - ex2f(fmaf(sqapx(q), C50F, -cL[r]));
            float a2 = fmaf(fx[r], J1.x, fmaf(fy[r], J1.y, fz[r]*J1.z));
            float p = ex2f(fmaf(a2, wgt, -J0.w));
            o0[r] = fmaf(p, J2.x, o0[r]);
            o1[r] = fmaf(p, J2.y, o1[r]);
            o2[r] = fmaf(p, J2.z, o2[r]);
        }
    }
    #pragma unroll
    for (int r = 0; r < 4; r++) {
        float v0 = wsum(o0[r]), v1 = wsum(o1[r]), v2 = wsum(o2[r]);
        if (lane == 0) {
            sO[sp][rg*4 + r][0] = v0;
            sO[sp][rg*4 + r][1] = v1;
            sO[sp][rg*4 + r][2] = v2;
        }
    }
    __syncthreads();
    if (threadIdx.x < 24) {
        int r = threadIdx.x / 3, ch = threadIdx.x % 3;
        float v = sO[0][r][ch] + sO[1][r][ch] + sO[2][r][ch] + sO[3][r][ch];
        out[b*NPIX*3 + (blockIdx.y*8 + r)*3 + ch] = v;
    }
}

// ---------------------------------------------------------------------------
extern "C" void kernel_launch(void* const* d_in, const int* in_sizes, int n_in,
                              void* d_out, int out_size) {
    const float* f_tar = (const float*)d_in[0];
    const float* f_src = (const float*)d_in[1];
    const float* Km    = (const float*)d_in[2];
    const float* Rm    = (const float*)d_in[3];
    const float* tv    = (const float*)d_in[4];
    float* out = (float*)d_out;

    k_pre<<<BT, 256>>>(f_tar, f_src, Km, Rm, tv);
    k_rowstats<<<dim3(BT, NPIX/8), 256>>>();
    k_colstats<<<dim3(BT, NPIX/8), 256>>>();
    k_out<<<dim3(BT, NPIX/8), 256>>>(out);
}